// round 4
// baseline (speedup 1.0000x reference)
#include <cuda_runtime.h>
#include <math.h>
#include <stdint.h>

// ---------------------------------------------------------------------------
// DeepseekV2MoE: T=1024, H=2048, I=1408, E=16, top4 of 16 experts (grouped),
// shared expert IS=2816. All fp32.
//
// Strategy: sparse grouped GEMM (only selected experts), deterministic
// compaction (no atomics anywhere), fused SiLU epilogues, final gather-add.
// ---------------------------------------------------------------------------

#define T_TOK 1024
#define HID   2048
#define IMID  1408
#define NEXP  16
#define ISH   2816
#define NGROUP 4
#define TOPKG  2
#define TOPK   4
#define ROUTED_SCALING 2.5f

// GEMM tiling
#define BM 64
#define BN 64
#define BK 16

// ---------------- scratch (device globals; allocation-free) ----------------
__device__ float g_act [(size_t)NEXP * T_TOK * IMID];   // routed silu(g)*u*w   (~92 MB)
__device__ float g_down[(size_t)NEXP * T_TOK * HID];    // routed down output   (~134 MB)
__device__ float g_sact[(size_t)T_TOK * ISH];           // shared silu(g)*u     (~11.5 MB)
__device__ int   g_topk_ids[T_TOK * TOPK];
__device__ float g_topk_w  [T_TOK * TOPK];
__device__ int   g_tok [NEXP * T_TOK];
__device__ float g_wt  [NEXP * T_TOK];
__device__ int   g_counts[NEXP];
__device__ int   g_slot[T_TOK * TOPK];

// ---------------------------------------------------------------------------
// K1: router. One block per token, 256 threads.
// ---------------------------------------------------------------------------
__global__ void router_kernel(const float* __restrict__ x,
                              const float* __restrict__ gw,
                              const float* __restrict__ bias)
{
    const int t   = blockIdx.x;
    const int tid = threadIdx.x;
    const int lane = tid & 31;
    const int wid  = tid >> 5;

    float acc[NEXP];
    #pragma unroll
    for (int e = 0; e < NEXP; e++) acc[e] = 0.f;

    const float* xr = x + (size_t)t * HID;
    for (int h = tid; h < HID; h += 256) {
        float xv = xr[h];
        #pragma unroll
        for (int e = 0; e < NEXP; e++)
            acc[e] = fmaf(xv, gw[(size_t)e * HID + h], acc[e]);
    }

    __shared__ float sred[8][NEXP];
    __shared__ float slog[NEXP];
    #pragma unroll
    for (int e = 0; e < NEXP; e++) {
        float v = acc[e];
        #pragma unroll
        for (int o = 16; o > 0; o >>= 1) v += __shfl_down_sync(0xffffffffu, v, o);
        if (lane == 0) sred[wid][e] = v;
    }
    __syncthreads();
    if (tid < NEXP) {
        float s = 0.f;
        #pragma unroll
        for (int w = 0; w < 8; w++) s += sred[w][tid];
        slog[tid] = s;
    }
    __syncthreads();

    if (tid == 0) {
        float sc[NEXP], sb[NEXP];
        #pragma unroll
        for (int e = 0; e < NEXP; e++) {
            sc[e] = 1.f / (1.f + expf(-slog[e]));
            sb[e] = sc[e] + bias[e];
        }
        // group score = sum of top-2 within each group of 4
        float gsc[NGROUP];
        #pragma unroll
        for (int g = 0; g < NGROUP; g++) {
            float m1 = -1e30f, m2 = -1e30f;
            #pragma unroll
            for (int j = 0; j < 4; j++) {
                float v = sb[g * 4 + j];
                if (v > m1) { m2 = m1; m1 = v; } else if (v > m2) m2 = v;
            }
            gsc[g] = m1 + m2;
        }
        int bg1 = 0;
        for (int g = 1; g < NGROUP; g++) if (gsc[g] > gsc[bg1]) bg1 = g;
        int bg2 = -1;
        for (int g = 0; g < NGROUP; g++)
            if (g != bg1 && (bg2 < 0 || gsc[g] > gsc[bg2])) bg2 = g;

        bool allowed[NEXP], used[NEXP];
        #pragma unroll
        for (int e = 0; e < NEXP; e++) {
            int g = e >> 2;
            allowed[e] = (g == bg1) || (g == bg2);
            used[e] = false;
        }
        int ids[TOPK];
        #pragma unroll
        for (int k = 0; k < TOPK; k++) {
            float best = -1e30f; int bi = -1;
            for (int e = 0; e < NEXP; e++)
                if (allowed[e] && !used[e] && sb[e] > best) { best = sb[e]; bi = e; }
            ids[k] = bi; used[bi] = true;
        }
        float ws = 0.f;
        #pragma unroll
        for (int k = 0; k < TOPK; k++) ws += sc[ids[k]];
        float inv = 1.f / ws;
        #pragma unroll
        for (int k = 0; k < TOPK; k++) {
            g_topk_ids[t * TOPK + k] = ids[k];
            g_topk_w  [t * TOPK + k] = sc[ids[k]] * inv;
        }
    }
}

// ---------------------------------------------------------------------------
// K2: deterministic per-expert compaction (one block of 1024 threads / expert)
// ---------------------------------------------------------------------------
__global__ void compact_kernel()
{
    const int e = blockIdx.x;
    const int t = threadIdx.x;

    int kf = -1;
    #pragma unroll
    for (int k = 0; k < TOPK; k++)
        if (g_topk_ids[t * TOPK + k] == e) kf = k;
    int flag = (kf >= 0) ? 1 : 0;

    __shared__ int s[T_TOK];
    s[t] = flag;
    __syncthreads();
    for (int off = 1; off < T_TOK; off <<= 1) {
        int v = (t >= off) ? s[t - off] : 0;
        __syncthreads();
        s[t] += v;
        __syncthreads();
    }
    int pos = s[t] - flag;
    if (flag) {
        g_tok[e * T_TOK + pos] = t;
        g_wt [e * T_TOK + pos] = g_topk_w[t * TOPK + kf] * ROUTED_SCALING;
        g_slot[t * TOPK + kf]  = e * T_TOK + pos;
    }
    if (t == T_TOK - 1) g_counts[e] = s[T_TOK - 1];
}

// ---------------------------------------------------------------------------
// K3: routed gate_up grouped GEMM + fused silu(g)*u*wt
// grid: (IMID/BN=22, T_TOK/BM=16, NEXP=16), 256 threads
// ---------------------------------------------------------------------------
__global__ void routed_gateup_kernel(const float* __restrict__ x,
                                     const float* __restrict__ wgu)
{
    const int e    = blockIdx.z;
    const int n    = g_counts[e];
    const int row0 = blockIdx.y * BM;
    if (row0 >= n) return;
    const int i0  = blockIdx.x * BN;
    const int tid = threadIdx.x;

    __shared__ float As[BK][BM];
    __shared__ float Bg[BK][BN];
    __shared__ float Bu[BK][BN];
    __shared__ int   stok[BM];
    __shared__ float swt[BM];

    if (tid < BM) {
        int r = row0 + tid;
        if (r < n) { stok[tid] = g_tok[e * T_TOK + r]; swt[tid] = g_wt[e * T_TOK + r]; }
        else       { stok[tid] = 0;                    swt[tid] = 0.f; }
    }
    __syncthreads();

    const float* wbase = wgu + (size_t)e * HID * (2 * IMID);

    float accg[4][4], accu[4][4];
    #pragma unroll
    for (int i = 0; i < 4; i++)
        #pragma unroll
        for (int j = 0; j < 4; j++) { accg[i][j] = 0.f; accu[i][j] = 0.f; }

    const int am = tid >> 2;         // 0..63
    const int ak = (tid & 3) * 4;    // 0,4,8,12
    const int bk = tid >> 4;         // 0..15
    const int bc = (tid & 15) * 4;   // 0..60
    const int ty = tid >> 4;         // 0..15
    const int tx = tid & 15;         // 0..15
    const bool arow_ok = (row0 + am < n);
    const size_t abase = (size_t)stok[am] * HID;

    for (int k0 = 0; k0 < HID; k0 += BK) {
        float4 av = make_float4(0.f, 0.f, 0.f, 0.f);
        if (arow_ok)
            av = *reinterpret_cast<const float4*>(x + abase + k0 + ak);
        As[ak + 0][am] = av.x; As[ak + 1][am] = av.y;
        As[ak + 2][am] = av.z; As[ak + 3][am] = av.w;

        const float* bp = wbase + (size_t)(k0 + bk) * (2 * IMID) + i0 + bc;
        *reinterpret_cast<float4*>(&Bg[bk][bc]) = *reinterpret_cast<const float4*>(bp);
        *reinterpret_cast<float4*>(&Bu[bk][bc]) = *reinterpret_cast<const float4*>(bp + IMID);
        __syncthreads();

        #pragma unroll
        for (int kk = 0; kk < BK; kk++) {
            float a[4], bg[4], bu[4];
            *reinterpret_cast<float4*>(a)  = *reinterpret_cast<const float4*>(&As[kk][ty * 4]);
            *reinterpret_cast<float4*>(bg) = *reinterpret_cast<const float4*>(&Bg[kk][tx * 4]);
            *reinterpret_cast<float4*>(bu) = *reinterpret_cast<const float4*>(&Bu[kk][tx * 4]);
            #pragma unroll
            for (int i = 0; i < 4; i++)
                #pragma unroll
                for (int j = 0; j < 4; j++) {
                    accg[i][j] = fmaf(a[i], bg[j], accg[i][j]);
                    accu[i][j] = fmaf(a[i], bu[j], accu[i][j]);
                }
        }
        __syncthreads();
    }

    #pragma unroll
    for (int i = 0; i < 4; i++) {
        int r = row0 + ty * 4 + i;
        if (r >= n) continue;
        float w = swt[ty * 4 + i];
        float v[4];
        #pragma unroll
        for (int j = 0; j < 4; j++) {
            float g = accg[i][j];
            float u = accu[i][j];
            v[j] = (g / (1.f + __expf(-g))) * u * w;
        }
        float* op = g_act + ((size_t)(e * T_TOK + r)) * IMID + i0 + tx * 4;
        *reinterpret_cast<float4*>(op) = make_float4(v[0], v[1], v[2], v[3]);
    }
}

// ---------------------------------------------------------------------------
// K4: routed down grouped GEMM: [n_e, IMID] x [IMID, HID] -> g_down (per slot)
// grid: (HID/BN=32, 16, NEXP)
// ---------------------------------------------------------------------------
__global__ void routed_down_kernel(const float* __restrict__ wd)
{
    const int e    = blockIdx.z;
    const int n    = g_counts[e];
    const int row0 = blockIdx.y * BM;
    if (row0 >= n) return;
    const int h0  = blockIdx.x * BN;
    const int tid = threadIdx.x;

    __shared__ float As[BK][BM];
    __shared__ float Bs[BK][BN];

    const float* wbase = wd + (size_t)e * IMID * HID;

    float acc[4][4];
    #pragma unroll
    for (int i = 0; i < 4; i++)
        #pragma unroll
        for (int j = 0; j < 4; j++) acc[i][j] = 0.f;

    const int am = tid >> 2;
    const int ak = (tid & 3) * 4;
    const int bk = tid >> 4;
    const int bc = (tid & 15) * 4;
    const int ty = tid >> 4;
    const int tx = tid & 15;
    const bool arow_ok = (row0 + am < n);
    const size_t abase = ((size_t)(e * T_TOK + row0 + am)) * IMID;

    for (int k0 = 0; k0 < IMID; k0 += BK) {
        float4 av = make_float4(0.f, 0.f, 0.f, 0.f);
        if (arow_ok)
            av = *reinterpret_cast<const float4*>(g_act + abase + k0 + ak);
        As[ak + 0][am] = av.x; As[ak + 1][am] = av.y;
        As[ak + 2][am] = av.z; As[ak + 3][am] = av.w;

        const float* bp = wbase + (size_t)(k0 + bk) * HID + h0 + bc;
        *reinterpret_cast<float4*>(&Bs[bk][bc]) = *reinterpret_cast<const float4*>(bp);
        __syncthreads();

        #pragma unroll
        for (int kk = 0; kk < BK; kk++) {
            float a[4], b[4];
            *reinterpret_cast<float4*>(a) = *reinterpret_cast<const float4*>(&As[kk][ty * 4]);
            *reinterpret_cast<float4*>(b) = *reinterpret_cast<const float4*>(&Bs[kk][tx * 4]);
            #pragma unroll
            for (int i = 0; i < 4; i++)
                #pragma unroll
                for (int j = 0; j < 4; j++)
                    acc[i][j] = fmaf(a[i], b[j], acc[i][j]);
        }
        __syncthreads();
    }

    #pragma unroll
    for (int i = 0; i < 4; i++) {
        int r = row0 + ty * 4 + i;
        if (r >= n) continue;
        float* op = g_down + ((size_t)(e * T_TOK + r)) * HID + h0 + tx * 4;
        *reinterpret_cast<float4*>(op) = make_float4(acc[i][0], acc[i][1], acc[i][2], acc[i][3]);
    }
}

// ---------------------------------------------------------------------------
// K5: shared expert gate_up: [T, H] x [H, 2*ISH] + fused silu(g)*u -> g_sact
// grid: (ISH/BN=44, T/BM=16)
// ---------------------------------------------------------------------------
__global__ void shared_gateup_kernel(const float* __restrict__ x,
                                     const float* __restrict__ sgu)
{
    const int row0 = blockIdx.y * BM;
    const int i0   = blockIdx.x * BN;
    const int tid  = threadIdx.x;

    __shared__ float As[BK][BM];
    __shared__ float Bg[BK][BN];
    __shared__ float Bu[BK][BN];

    float accg[4][4], accu[4][4];
    #pragma unroll
    for (int i = 0; i < 4; i++)
        #pragma unroll
        for (int j = 0; j < 4; j++) { accg[i][j] = 0.f; accu[i][j] = 0.f; }

    const int am = tid >> 2;
    const int ak = (tid & 3) * 4;
    const int bk = tid >> 4;
    const int bc = (tid & 15) * 4;
    const int ty = tid >> 4;
    const int tx = tid & 15;
    const size_t abase = (size_t)(row0 + am) * HID;

    for (int k0 = 0; k0 < HID; k0 += BK) {
        float4 av = *reinterpret_cast<const float4*>(x + abase + k0 + ak);
        As[ak + 0][am] = av.x; As[ak + 1][am] = av.y;
        As[ak + 2][am] = av.z; As[ak + 3][am] = av.w;

        const float* bp = sgu + (size_t)(k0 + bk) * (2 * ISH) + i0 + bc;
        *reinterpret_cast<float4*>(&Bg[bk][bc]) = *reinterpret_cast<const float4*>(bp);
        *reinterpret_cast<float4*>(&Bu[bk][bc]) = *reinterpret_cast<const float4*>(bp + ISH);
        __syncthreads();

        #pragma unroll
        for (int kk = 0; kk < BK; kk++) {
            float a[4], bg[4], bu[4];
            *reinterpret_cast<float4*>(a)  = *reinterpret_cast<const float4*>(&As[kk][ty * 4]);
            *reinterpret_cast<float4*>(bg) = *reinterpret_cast<const float4*>(&Bg[kk][tx * 4]);
            *reinterpret_cast<float4*>(bu) = *reinterpret_cast<const float4*>(&Bu[kk][tx * 4]);
            #pragma unroll
            for (int i = 0; i < 4; i++)
                #pragma unroll
                for (int j = 0; j < 4; j++) {
                    accg[i][j] = fmaf(a[i], bg[j], accg[i][j]);
                    accu[i][j] = fmaf(a[i], bu[j], accu[i][j]);
                }
        }
        __syncthreads();
    }

    #pragma unroll
    for (int i = 0; i < 4; i++) {
        int r = row0 + ty * 4 + i;
        float v[4];
        #pragma unroll
        for (int j = 0; j < 4; j++) {
            float g = accg[i][j];
            float u = accu[i][j];
            v[j] = (g / (1.f + __expf(-g))) * u;
        }
        float* op = g_sact + (size_t)r * ISH + i0 + tx * 4;
        *reinterpret_cast<float4*>(op) = make_float4(v[0], v[1], v[2], v[3]);
    }
}

// ---------------------------------------------------------------------------
// K6: shared expert down: [T, ISH] x [ISH, HID] -> d_out (full overwrite)
// grid: (HID/BN=32, T/BM=16)
// ---------------------------------------------------------------------------
__global__ void shared_down_kernel(const float* __restrict__ sd,
                                   float* __restrict__ out)
{
    const int row0 = blockIdx.y * BM;
    const int h0   = blockIdx.x * BN;
    const int tid  = threadIdx.x;

    __shared__ float As[BK][BM];
    __shared__ float Bs[BK][BN];

    float acc[4][4];
    #pragma unroll
    for (int i = 0; i < 4; i++)
        #pragma unroll
        for (int j = 0; j < 4; j++) acc[i][j] = 0.f;

    const int am = tid >> 2;
    const int ak = (tid & 3) * 4;
    const int bk = tid >> 4;
    const int bc = (tid & 15) * 4;
    const int ty = tid >> 4;
    const int tx = tid & 15;
    const size_t abase = (size_t)(row0 + am) * ISH;

    for (int k0 = 0; k0 < ISH; k0 += BK) {
        float4 av = *reinterpret_cast<const float4*>(g_sact + abase + k0 + ak);
        As[ak + 0][am] = av.x; As[ak + 1][am] = av.y;
        As[ak + 2][am] = av.z; As[ak + 3][am] = av.w;

        const float* bp = sd + (size_t)(k0 + bk) * HID + h0 + bc;
        *reinterpret_cast<float4*>(&Bs[bk][bc]) = *reinterpret_cast<const float4*>(bp);
        __syncthreads();

        #pragma unroll
        for (int kk = 0; kk < BK; kk++) {
            float a[4], b[4];
            *reinterpret_cast<float4*>(a) = *reinterpret_cast<const float4*>(&As[kk][ty * 4]);
            *reinterpret_cast<float4*>(b) = *reinterpret_cast<const float4*>(&Bs[kk][tx * 4]);
            #pragma unroll
            for (int i = 0; i < 4; i++)
                #pragma unroll
                for (int j = 0; j < 4; j++)
                    acc[i][j] = fmaf(a[i], b[j], acc[i][j]);
        }
        __syncthreads();
    }

    #pragma unroll
    for (int i = 0; i < 4; i++) {
        int r = row0 + ty * 4 + i;
        float* op = out + (size_t)r * HID + h0 + tx * 4;
        *reinterpret_cast<float4*>(op) = make_float4(acc[i][0], acc[i][1], acc[i][2], acc[i][3]);
    }
}

// ---------------------------------------------------------------------------
// K7: final combine: out[t] += sum_k g_down[slot[t][k]]
// ---------------------------------------------------------------------------
__global__ void combine_kernel(float* __restrict__ out)
{
    const int idx = blockIdx.x * blockDim.x + threadIdx.x;  // over T*HID/4
    const int t  = idx >> 9;            // HID/4 = 512 float4 per row
    const int hc = (idx & 511) * 4;

    float4 acc = *reinterpret_cast<const float4*>(out + (size_t)t * HID + hc);
    #pragma unroll
    for (int k = 0; k < TOPK; k++) {
        int s = g_slot[t * TOPK + k];
        float4 v = *reinterpret_cast<const float4*>(g_down + (size_t)s * HID + hc);
        acc.x += v.x; acc.y += v.y; acc.z += v.z; acc.w += v.w;
    }
    *reinterpret_cast<float4*>(out + (size_t)t * HID + hc) = acc;
}

// ---------------------------------------------------------------------------
extern "C" void kernel_launch(void* const* d_in, const int* in_sizes, int n_in,
                              void* d_out, int out_size)
{
    const float* x    = (const float*)d_in[0];  // [1024, 2048]
    const float* gw   = (const float*)d_in[1];  // [16, 2048]
    const float* bias = (const float*)d_in[2];  // [16]
    const float* wgu  = (const float*)d_in[3];  // [16, 2048, 2816]
    const float* wd   = (const float*)d_in[4];  // [16, 1408, 2048]
    const float* sgu  = (const float*)d_in[5];  // [2048, 5632]
    const float* sd   = (const float*)d_in[6];  // [2816, 2048]
    float* out = (float*)d_out;                 // [1024, 2048]

    (void)in_sizes; (void)n_in; (void)out_size;

    router_kernel<<<T_TOK, 256>>>(x, gw, bias);
    compact_kernel<<<NEXP, T_TOK>>>();

    {
        dim3 grid(IMID / BN, T_TOK / BM, NEXP);   // (22, 16, 16)
        routed_gateup_kernel<<<grid, 256>>>(x, wgu);
    }
    {
        dim3 grid(ISH / BN, T_TOK / BM);          // (44, 16)
        shared_gateup_kernel<<<grid, 256>>>(x, sgu);
    }
    {
        dim3 grid(HID / BN, T_TOK / BM, NEXP);    // (32, 16, 16)
        routed_down_kernel<<<grid, 256>>>(wd);
    }
    {
        dim3 grid(HID / BN, T_TOK / BM);          // (32, 16)
        shared_down_kernel<<<grid, 256>>>(sd, out);
    }
    {
        int total = T_TOK * (HID / 4);            // 524288
        combine_kernel<<<total / 256, 256>>>(out);
    }
}